// round 2
// baseline (speedup 1.0000x reference)
#include <cuda_runtime.h>
#include <cstdint>

#define NN 50000
#define EE 800000
#define DD 128
#define NMAT (DD*DD)

typedef unsigned long long u64;

// ---------------- scratch (static device globals; no runtime alloc) ----------------
__device__ float g_agg[NN*DD];
__device__ float g_x1[NN*DD];
__device__ float g_x2[NN*DD];
__device__ int   g_cnt[NN];
__device__ int   g_off[NN+1];
__device__ int   g_cursor[NN];
__device__ int   g_csr[EE];
__device__ float g_WlT[2*NMAT];
__device__ float g_WrT[2*NMAT];
__device__ float g_WT[NMAT];
__device__ int   g_is64;

// ---------------- packed f32x2 helpers ----------------
__device__ __forceinline__ u64 pack2(float a, float b) {
    u64 r;
    asm("mov.b64 %0, {%1, %2};" : "=l"(r) : "r"(__float_as_uint(a)), "r"(__float_as_uint(b)));
    return r;
}
__device__ __forceinline__ void fma2(u64& d, u64 a, u64 b) {
    asm("fma.rn.f32x2 %0, %1, %2, %0;" : "+l"(d) : "l"(a), "l"(b));
}
__device__ __forceinline__ float2 unpack2(u64 v) {
    unsigned lo, hi;
    asm("mov.b64 {%0, %1}, %2;" : "=r"(lo), "=r"(hi) : "l"(v));
    return make_float2(__uint_as_float(lo), __uint_as_float(hi));
}

// ---------------- edge_index dtype detection ----------------
// JAX with x64 disabled silently downcasts int64 -> int32. Detect which dtype
// the buffer actually holds: interpret first 64 values as int64; if all are in
// [0, NN) it is int64 (high words would be random nonzero indices otherwise).
__global__ void k_detect(const void* __restrict__ ei) {
    if (threadIdx.x == 0 && blockIdx.x == 0) {
        const long long* p = (const long long*)ei;
        int ok = 1;
        for (int i = 0; i < 64; i++) {
            long long v = p[i];
            if (v < 0 || v >= NN) { ok = 0; break; }
        }
        g_is64 = ok;
    }
}

__device__ __forceinline__ int load_idx(const void* ei, int pos, int is64) {
    if (is64) return (int)((const long long*)ei)[pos];
    return ((const int*)ei)[pos];
}

// ---------------- CSR construction ----------------
__global__ void k_zero_cnt() {
    for (int i = blockIdx.x*blockDim.x + threadIdx.x; i < NN; i += gridDim.x*blockDim.x)
        g_cnt[i] = 0;
}

__global__ void k_count(const void* __restrict__ ei) {
    int i = blockIdx.x*blockDim.x + threadIdx.x;
    if (i < EE) {
        int dst = load_idx(ei, EE + i, g_is64);
        if ((unsigned)dst < NN) atomicAdd(&g_cnt[dst], 1);
    }
}

// single-block exclusive scan over g_cnt -> g_off, g_cursor
__global__ void k_scan() {
    __shared__ int sh[1024];
    __shared__ int s_carry;
    int tid = threadIdx.x;
    if (tid == 0) s_carry = 0;
    __syncthreads();
    for (int base = 0; base < NN; base += 1024) {
        int i = base + tid;
        int v = (i < NN) ? g_cnt[i] : 0;
        sh[tid] = v;
        __syncthreads();
        #pragma unroll
        for (int s = 1; s < 1024; s <<= 1) {
            int t = (tid >= s) ? sh[tid - s] : 0;
            __syncthreads();
            sh[tid] += t;
            __syncthreads();
        }
        int incl = sh[tid] + s_carry;
        if (i < NN) {
            int excl = incl - v;
            g_off[i]    = excl;
            g_cursor[i] = excl;
        }
        __syncthreads();
        if (tid == 1023) s_carry = incl;
        __syncthreads();
    }
    if (tid == 0) g_off[NN] = s_carry;
}

__global__ void k_scatter(const void* __restrict__ ei) {
    int i = blockIdx.x*blockDim.x + threadIdx.x;
    if (i < EE) {
        int is64 = g_is64;
        int src = load_idx(ei, i, is64);
        int dst = load_idx(ei, EE + i, is64);
        if ((unsigned)dst < NN && (unsigned)src < NN) {
            int pos = atomicAdd(&g_cursor[dst], 1);
            if ((unsigned)pos < EE) g_csr[pos] = src;
        }
    }
}

// ---------------- weight transpose (once per launch, keeps GEMM smem loads conflict-free)
// out[k][j] = in[j][k], per 128x128 matrix; blockIdx.y = matrix index
__global__ void k_transpose(const float* __restrict__ in, float* __restrict__ out) {
    __shared__ float t[32][33];
    const float* inp  = in  + blockIdx.y * NMAT;
    float*       outp = out + blockIdx.y * NMAT;
    int bx = blockIdx.x & 3, by = blockIdx.x >> 2;
    int x = bx*32 + threadIdx.x;
    #pragma unroll
    for (int i = threadIdx.y; i < 32; i += 8)
        t[i][threadIdx.x] = inp[(by*32 + i)*DD + x];
    __syncthreads();
    int xo = by*32 + threadIdx.x;
    #pragma unroll
    for (int i = threadIdx.y; i < 32; i += 8)
        outp[(bx*32 + i)*DD + xo] = t[threadIdx.x][i];
}

// ---------------- max-aggregation: one warp per node, float4 per lane ----------------
__global__ void k_aggregate(const float* __restrict__ x, float* __restrict__ agg) {
    int w    = blockIdx.x * 8 + (threadIdx.x >> 5);
    int lane = threadIdx.x & 31;
    if (w >= NN) return;
    int beg = g_off[w], end = g_off[w+1];
    const float NEG = __int_as_float(0xff800000);
    float4 m = make_float4(NEG, NEG, NEG, NEG);
    const float4* xv = (const float4*)x;
    int e = beg;
    for (; e + 4 <= end; e += 4) {
        int s0 = g_csr[e], s1 = g_csr[e+1], s2 = g_csr[e+2], s3 = g_csr[e+3];
        float4 v0 = xv[s0*32 + lane];
        float4 v1 = xv[s1*32 + lane];
        float4 v2 = xv[s2*32 + lane];
        float4 v3 = xv[s3*32 + lane];
        m.x = fmaxf(m.x, fmaxf(fmaxf(v0.x, v1.x), fmaxf(v2.x, v3.x)));
        m.y = fmaxf(m.y, fmaxf(fmaxf(v0.y, v1.y), fmaxf(v2.y, v3.y)));
        m.z = fmaxf(m.z, fmaxf(fmaxf(v0.z, v1.z), fmaxf(v2.z, v3.z)));
        m.w = fmaxf(m.w, fmaxf(fmaxf(v0.w, v1.w), fmaxf(v2.w, v3.w)));
    }
    for (; e < end; e++) {
        int s = g_csr[e];
        float4 v = xv[s*32 + lane];
        m.x = fmaxf(m.x, v.x);
        m.y = fmaxf(m.y, v.y);
        m.z = fmaxf(m.z, v.z);
        m.w = fmaxf(m.w, v.w);
    }
    if (beg == end) m = make_float4(0.f, 0.f, 0.f, 0.f);
    ((float4*)agg)[w*32 + lane] = m;
}

// ---------------- fused GEMM: out = relu?( A1@W1^T [+ A2@W2^T] + bias ) ----------------
// Block tile 128 rows x 128 cols, 256 threads, thread tile 8x8, f32x2 packed FMAs.
__device__ __forceinline__ void load_tile(float* dst, const float* __restrict__ src,
                                          int row0, int nrows) {
    int tid = threadIdx.x;
    #pragma unroll
    for (int it = 0; it < 16; it++) {
        int idx = it*256 + tid;           // 0..4095 float4s
        int r = idx >> 5;
        float4 v = make_float4(0.f, 0.f, 0.f, 0.f);
        int row = row0 + r;
        if (row < nrows) v = ((const float4*)src)[row*32 + (idx & 31)];
        ((float4*)dst)[idx] = v;
    }
}

__device__ __forceinline__ void load_w(float* dst, const float* __restrict__ src) {
    int tid = threadIdx.x;
    #pragma unroll
    for (int it = 0; it < 16; it++) {
        int idx = it*256 + tid;
        ((float4*)dst)[idx] = ((const float4*)src)[idx];
    }
}

__device__ __forceinline__ void gemm_pass(const float* __restrict__ Ws,
                                          const float* __restrict__ As,
                                          int ty, int tx, u64 acc[8][4]) {
    #pragma unroll 1
    for (int k = 0; k < DD; k += 4) {
        u64 w[4][4];
        #pragma unroll
        for (int kk = 0; kk < 4; kk++) {
            const ulonglong2* wp = (const ulonglong2*)(Ws + (k+kk)*DD + tx*8);
            ulonglong2 wa = wp[0];
            ulonglong2 wb = wp[1];
            w[kk][0] = wa.x; w[kk][1] = wa.y; w[kk][2] = wb.x; w[kk][3] = wb.y;
        }
        #pragma unroll
        for (int r = 0; r < 8; r++) {
            float4 av = *(const float4*)(As + (ty*8 + r)*DD + k);
            u64 a0 = pack2(av.x, av.x);
            u64 a1 = pack2(av.y, av.y);
            u64 a2 = pack2(av.z, av.z);
            u64 a3 = pack2(av.w, av.w);
            #pragma unroll
            for (int c = 0; c < 4; c++) {
                fma2(acc[r][c], a0, w[0][c]);
                fma2(acc[r][c], a1, w[1][c]);
                fma2(acc[r][c], a2, w[2][c]);
                fma2(acc[r][c], a3, w[3][c]);
            }
        }
    }
}

template<bool HAS2, bool RELU>
__global__ __launch_bounds__(256)
void k_gemm(const float* __restrict__ A1, const float* __restrict__ A2,
            const float* __restrict__ W1T, const float* __restrict__ W2T,
            const float* __restrict__ bias, float* __restrict__ out, int nrows)
{
    extern __shared__ float sm[];
    float* Ws  = sm;              // 128x128 (one weight matrix at a time, pre-transposed)
    float* As1 = sm + NMAT;       // 128x128 A1 tile
    float* As2 = As1 + NMAT;      // 128x128 A2 tile (HAS2 only)

    int row0 = blockIdx.x * 128;
    load_tile(As1, A1, row0, nrows);
    if (HAS2) load_tile(As2, A2, row0, nrows);
    load_w(Ws, W1T);
    __syncthreads();

    int tx = threadIdx.x & 15;    // 16 col groups * 8 cols
    int ty = threadIdx.x >> 4;    // 16 row groups * 8 rows
    u64 acc[8][4];
    #pragma unroll
    for (int r = 0; r < 8; r++)
        #pragma unroll
        for (int c = 0; c < 4; c++) acc[r][c] = 0ULL;

    gemm_pass(Ws, As1, ty, tx, acc);
    if (HAS2) {
        __syncthreads();
        load_w(Ws, W2T);
        __syncthreads();
        gemm_pass(Ws, As2, ty, tx, acc);
    }

    float bb[8];
    *(float4*)(bb)   = *(const float4*)(bias + tx*8);
    *(float4*)(bb+4) = *(const float4*)(bias + tx*8 + 4);

    #pragma unroll
    for (int r = 0; r < 8; r++) {
        int row = row0 + ty*8 + r;
        if (row < nrows) {
            float o[8];
            #pragma unroll
            for (int c = 0; c < 4; c++) {
                float2 p = unpack2(acc[r][c]);
                o[2*c] = p.x; o[2*c+1] = p.y;
            }
            #pragma unroll
            for (int c = 0; c < 8; c++) {
                o[c] += bb[c];
                if (RELU) o[c] = fmaxf(o[c], 0.f);
            }
            float* op = out + row*DD + tx*8;
            *(float4*)op       = make_float4(o[0], o[1], o[2], o[3]);
            *(float4*)(op + 4) = make_float4(o[4], o[5], o[6], o[7]);
        }
    }
}

// ---------------- launch ----------------
extern "C" void kernel_launch(void* const* d_in, const int* in_sizes, int n_in,
                              void* d_out, int out_size) {
    const float* x  = (const float*)d_in[0];
    const void*  ei = d_in[1];
    const float* Wl = (const float*)d_in[2];
    const float* bl = (const float*)d_in[3];
    const float* Wr = (const float*)d_in[4];
    const float* W  = (const float*)d_in[5];
    const float* b  = (const float*)d_in[6];
    float* out = (float*)d_out;

    void *pa, *p1, *p2, *pl, *pr, *pw;
    cudaGetSymbolAddress(&pa, g_agg);
    cudaGetSymbolAddress(&p1, g_x1);
    cudaGetSymbolAddress(&p2, g_x2);
    cudaGetSymbolAddress(&pl, g_WlT);
    cudaGetSymbolAddress(&pr, g_WrT);
    cudaGetSymbolAddress(&pw, g_WT);
    float* agg = (float*)pa;
    float* x1  = (float*)p1;
    float* x2  = (float*)p2;
    float* WlT = (float*)pl;
    float* WrT = (float*)pr;
    float* WT  = (float*)pw;

    const int smem2 = 3*NMAT*(int)sizeof(float);   // 196608
    const int smem1 = 2*NMAT*(int)sizeof(float);   // 131072
    cudaFuncSetAttribute(k_gemm<true,true>,   cudaFuncAttributeMaxDynamicSharedMemorySize, smem2);
    cudaFuncSetAttribute(k_gemm<false,false>, cudaFuncAttributeMaxDynamicSharedMemorySize, smem1);

    // CSR build
    k_detect <<<1, 32>>>(ei);
    k_zero_cnt<<<98, 512>>>();
    k_count  <<<(EE+255)/256, 256>>>(ei);
    k_scan   <<<1, 1024>>>();
    k_scatter<<<(EE+255)/256, 256>>>(ei);

    // weight transposes (once per launch)
    k_transpose<<<dim3(16,2), dim3(32,8)>>>(Wl, WlT);
    k_transpose<<<dim3(16,2), dim3(32,8)>>>(Wr, WrT);
    k_transpose<<<dim3(16,1), dim3(32,8)>>>(W,  WT);

    const int gemm_blocks = (NN + 127) / 128;

    // layer 0
    k_aggregate<<<(NN+7)/8, 256>>>(x, agg);
    k_gemm<true,true><<<gemm_blocks, 256, smem2>>>(agg, x, WlT, WrT, bl, x1, NN);
    // layer 1
    k_aggregate<<<(NN+7)/8, 256>>>(x1, agg);
    k_gemm<true,true><<<gemm_blocks, 256, smem2>>>(agg, x1, WlT+NMAT, WrT+NMAT, bl+DD, x2, NN);
    // final linear
    k_gemm<false,false><<<gemm_blocks, 256, smem1>>>(x2, nullptr, WT, nullptr, b, out, NN);
}

// round 3
// speedup vs baseline: 1.2106x; 1.2106x over previous
#include <cuda_runtime.h>
#include <cstdint>

#define NN 50000
#define EE 800000
#define DD 128
#define NMAT (DD*DD)
#define SCAN_B 1024
#define NBLK ((NN + SCAN_B - 1) / SCAN_B)   // 49

typedef unsigned long long u64;

// ---------------- scratch (static device globals; no runtime alloc) ----------------
__device__ float g_agg[NN*DD];
__device__ float g_x1[NN*DD];
__device__ float g_x2[NN*DD];
__device__ int   g_cnt[NN];
__device__ int   g_off[NN+1];
__device__ int   g_cursor[NN];
__device__ int   g_csr[EE];
__device__ int   g_bsum[64];
__device__ int   g_bbase[64];
__device__ float g_WlT[2*NMAT];
__device__ float g_WrT[2*NMAT];
__device__ float g_WT[NMAT];
__device__ int   g_is64;

// ---------------- packed f32x2 helpers ----------------
__device__ __forceinline__ u64 pack2(float a, float b) {
    u64 r;
    asm("mov.b64 %0, {%1, %2};" : "=l"(r) : "r"(__float_as_uint(a)), "r"(__float_as_uint(b)));
    return r;
}
__device__ __forceinline__ void fma2(u64& d, u64 a, u64 b) {
    asm("fma.rn.f32x2 %0, %1, %2, %0;" : "+l"(d) : "l"(a), "l"(b));
}
__device__ __forceinline__ float2 unpack2(u64 v) {
    unsigned lo, hi;
    asm("mov.b64 {%0, %1}, %2;" : "=r"(lo), "=r"(hi) : "l"(v));
    return make_float2(__uint_as_float(lo), __uint_as_float(hi));
}

// ---------------- init: dtype detection (parallel) + zero counters ----------------
// JAX x64-disabled downcasts int64->int32. Interpret first 64 values as int64;
// all in [0,NN) <=> really int64 (else high words are random nonzero indices).
__global__ void k_init(const void* __restrict__ ei) {
    __shared__ int s_ok[2];
    int tid = threadIdx.x;
    if (blockIdx.x == 0) {
        if (tid < 64) {
            long long v = ((const long long*)ei)[tid];
            unsigned ok = (v >= 0 && v < NN) ? 1u : 0u;
            unsigned m = __ballot_sync(0xffffffffu, ok);
            if ((tid & 31) == 0) s_ok[tid >> 5] = (m == 0xffffffffu);
        }
        __syncthreads();
        if (tid == 0) g_is64 = s_ok[0] & s_ok[1];
    }
    for (int i = blockIdx.x*blockDim.x + tid; i < NN; i += gridDim.x*blockDim.x)
        g_cnt[i] = 0;
}

__device__ __forceinline__ int load_idx(const void* ei, int pos, int is64) {
    if (is64) return (int)((const long long*)ei)[pos];
    return ((const int*)ei)[pos];
}

__global__ void k_count(const void* __restrict__ ei) {
    int i = blockIdx.x*blockDim.x + threadIdx.x;
    if (i < EE) {
        int dst = load_idx(ei, EE + i, g_is64);
        if ((unsigned)dst < NN) atomicAdd(&g_cnt[dst], 1);
    }
}

// ---------------- multi-block exclusive scan (3 tiny kernels) ----------------
// pass 1: per-block inclusive scan (warp shuffles), stash incl in g_off[i+1], totals in g_bsum
__global__ void k_scan1() {
    __shared__ int wsum[32];
    int tid  = threadIdx.x;
    int lane = tid & 31, wid = tid >> 5;
    int i = blockIdx.x*SCAN_B + tid;
    int v = (i < NN) ? g_cnt[i] : 0;
    int s = v;
    #pragma unroll
    for (int d = 1; d < 32; d <<= 1) {
        int t = __shfl_up_sync(0xffffffffu, s, d);
        if (lane >= d) s += t;
    }
    if (lane == 31) wsum[wid] = s;
    __syncthreads();
    if (wid == 0) {
        int ws = wsum[lane];
        #pragma unroll
        for (int d = 1; d < 32; d <<= 1) {
            int t = __shfl_up_sync(0xffffffffu, ws, d);
            if (lane >= d) ws += t;
        }
        wsum[lane] = ws;
    }
    __syncthreads();
    int incl = s + ((wid > 0) ? wsum[wid-1] : 0);
    if (i < NN) g_off[i+1] = incl;               // temp: block-local inclusive
    if (tid == SCAN_B-1) g_bsum[blockIdx.x] = incl;
}

// pass 2: exclusive scan of 49 block sums
__global__ void k_scan2() {
    __shared__ int sh[64];
    int tid = threadIdx.x;
    int v = (tid < NBLK) ? g_bsum[tid] : 0;
    sh[tid] = v;
    __syncthreads();
    #pragma unroll
    for (int s = 1; s < 64; s <<= 1) {
        int t = (tid >= s) ? sh[tid - s] : 0;
        __syncthreads();
        sh[tid] += t;
        __syncthreads();
    }
    if (tid < NBLK) g_bbase[tid] = sh[tid] - v;
}

// pass 3: add block base, produce g_off (exclusive boundaries) + g_cursor
__global__ void k_scan3() {
    int i = blockIdx.x*SCAN_B + threadIdx.x;
    if (i < NN) {
        int incl = g_off[i+1] + g_bbase[blockIdx.x];
        g_off[i+1]  = incl;
        g_cursor[i] = incl - g_cnt[i];
    }
    if (i == 0) g_off[0] = 0;
}

__global__ void k_scatter(const void* __restrict__ ei) {
    int i = blockIdx.x*blockDim.x + threadIdx.x;
    if (i < EE) {
        int is64 = g_is64;
        int src = load_idx(ei, i, is64);
        int dst = load_idx(ei, EE + i, is64);
        if ((unsigned)dst < NN && (unsigned)src < NN) {
            int pos = atomicAdd(&g_cursor[dst], 1);
            if ((unsigned)pos < EE) g_csr[pos] = src;
        }
    }
}

// ---------------- weight transpose, all 5 matrices in one launch ----------------
__global__ void k_transpose(const float* __restrict__ Wl, const float* __restrict__ Wr,
                            const float* __restrict__ W) {
    __shared__ float t[32][33];
    int m = blockIdx.y;                 // 0,1: Wl  2,3: Wr  4: W
    const float* inp;
    float* outp;
    if (m < 2)      { inp = Wl + m*NMAT;     outp = g_WlT + m*NMAT; }
    else if (m < 4) { inp = Wr + (m-2)*NMAT; outp = g_WrT + (m-2)*NMAT; }
    else            { inp = W;               outp = g_WT; }
    int bx = blockIdx.x & 3, by = blockIdx.x >> 2;
    int x = bx*32 + threadIdx.x;
    #pragma unroll
    for (int i = threadIdx.y; i < 32; i += 8)
        t[i][threadIdx.x] = inp[(by*32 + i)*DD + x];
    __syncthreads();
    int xo = by*32 + threadIdx.x;
    #pragma unroll
    for (int i = threadIdx.y; i < 32; i += 8)
        outp[(bx*32 + i)*DD + xo] = t[threadIdx.x][i];
}

// ---------------- max-aggregation: one warp per node, float4 per lane ----------------
__global__ void k_aggregate(const float* __restrict__ x, float* __restrict__ agg) {
    int w    = blockIdx.x * 8 + (threadIdx.x >> 5);
    int lane = threadIdx.x & 31;
    if (w >= NN) return;
    int beg = g_off[w], end = g_off[w+1];
    const float NEG = __int_as_float(0xff800000);
    float4 m = make_float4(NEG, NEG, NEG, NEG);
    const float4* xv = (const float4*)x;
    int e = beg;
    for (; e + 4 <= end; e += 4) {
        int s0 = g_csr[e], s1 = g_csr[e+1], s2 = g_csr[e+2], s3 = g_csr[e+3];
        float4 v0 = xv[s0*32 + lane];
        float4 v1 = xv[s1*32 + lane];
        float4 v2 = xv[s2*32 + lane];
        float4 v3 = xv[s3*32 + lane];
        m.x = fmaxf(m.x, fmaxf(fmaxf(v0.x, v1.x), fmaxf(v2.x, v3.x)));
        m.y = fmaxf(m.y, fmaxf(fmaxf(v0.y, v1.y), fmaxf(v2.y, v3.y)));
        m.z = fmaxf(m.z, fmaxf(fmaxf(v0.z, v1.z), fmaxf(v2.z, v3.z)));
        m.w = fmaxf(m.w, fmaxf(fmaxf(v0.w, v1.w), fmaxf(v2.w, v3.w)));
    }
    for (; e < end; e++) {
        int s = g_csr[e];
        float4 v = xv[s*32 + lane];
        m.x = fmaxf(m.x, v.x);
        m.y = fmaxf(m.y, v.y);
        m.z = fmaxf(m.z, v.z);
        m.w = fmaxf(m.w, v.w);
    }
    if (beg == end) m = make_float4(0.f, 0.f, 0.f, 0.f);
    ((float4*)agg)[w*32 + lane] = m;
}

// ---------------- fused GEMM: out = relu?( A1@W1^T [+ A2@W2^T] + bias ) ----------------
// Block tile 128 rows x 128 cols, 256 threads, thread tile 8x8, f32x2 packed FMAs.
__device__ __forceinline__ void load_tile(float* dst, const float* __restrict__ src,
                                          int row0, int nrows) {
    int tid = threadIdx.x;
    #pragma unroll
    for (int it = 0; it < 16; it++) {
        int idx = it*256 + tid;           // 0..4095 float4s
        int r = idx >> 5;
        float4 v = make_float4(0.f, 0.f, 0.f, 0.f);
        int row = row0 + r;
        if (row < nrows) v = ((const float4*)src)[row*32 + (idx & 31)];
        ((float4*)dst)[idx] = v;
    }
}

__device__ __forceinline__ void load_w(float* dst, const float* __restrict__ src) {
    int tid = threadIdx.x;
    #pragma unroll
    for (int it = 0; it < 16; it++) {
        int idx = it*256 + tid;
        ((float4*)dst)[idx] = ((const float4*)src)[idx];
    }
}

__device__ __forceinline__ void gemm_pass(const float* __restrict__ Ws,
                                          const float* __restrict__ As,
                                          int ty, int tx, u64 acc[8][4]) {
    #pragma unroll 1
    for (int k = 0; k < DD; k += 4) {
        u64 w[4][4];
        #pragma unroll
        for (int kk = 0; kk < 4; kk++) {
            const ulonglong2* wp = (const ulonglong2*)(Ws + (k+kk)*DD + tx*8);
            ulonglong2 wa = wp[0];
            ulonglong2 wb = wp[1];
            w[kk][0] = wa.x; w[kk][1] = wa.y; w[kk][2] = wb.x; w[kk][3] = wb.y;
        }
        #pragma unroll
        for (int r = 0; r < 8; r++) {
            float4 av = *(const float4*)(As + (ty*8 + r)*DD + k);
            u64 a0 = pack2(av.x, av.x);
            u64 a1 = pack2(av.y, av.y);
            u64 a2 = pack2(av.z, av.z);
            u64 a3 = pack2(av.w, av.w);
            #pragma unroll
            for (int c = 0; c < 4; c++) {
                fma2(acc[r][c], a0, w[0][c]);
                fma2(acc[r][c], a1, w[1][c]);
                fma2(acc[r][c], a2, w[2][c]);
                fma2(acc[r][c], a3, w[3][c]);
            }
        }
    }
}

template<bool HAS2, bool RELU>
__global__ __launch_bounds__(256)
void k_gemm(const float* __restrict__ A1, const float* __restrict__ A2,
            const float* __restrict__ W1T, const float* __restrict__ W2T,
            const float* __restrict__ bias, float* __restrict__ out, int nrows)
{
    extern __shared__ float sm[];
    float* Ws  = sm;              // 128x128 (one weight matrix at a time, pre-transposed)
    float* As1 = sm + NMAT;       // 128x128 A1 tile
    float* As2 = As1 + NMAT;      // 128x128 A2 tile (HAS2 only)

    int row0 = blockIdx.x * 128;
    load_tile(As1, A1, row0, nrows);
    if (HAS2) load_tile(As2, A2, row0, nrows);
    load_w(Ws, W1T);
    __syncthreads();

    int tx = threadIdx.x & 15;    // 16 col groups * 8 cols
    int ty = threadIdx.x >> 4;    // 16 row groups * 8 rows
    u64 acc[8][4];
    #pragma unroll
    for (int r = 0; r < 8; r++)
        #pragma unroll
        for (int c = 0; c < 4; c++) acc[r][c] = 0ULL;

    gemm_pass(Ws, As1, ty, tx, acc);
    if (HAS2) {
        __syncthreads();
        load_w(Ws, W2T);
        __syncthreads();
        gemm_pass(Ws, As2, ty, tx, acc);
    }

    float bb[8];
    *(float4*)(bb)   = *(const float4*)(bias + tx*8);
    *(float4*)(bb+4) = *(const float4*)(bias + tx*8 + 4);

    #pragma unroll
    for (int r = 0; r < 8; r++) {
        int row = row0 + ty*8 + r;
        if (row < nrows) {
            float o[8];
            #pragma unroll
            for (int c = 0; c < 4; c++) {
                float2 p = unpack2(acc[r][c]);
                o[2*c] = p.x; o[2*c+1] = p.y;
            }
            #pragma unroll
            for (int c = 0; c < 8; c++) {
                o[c] += bb[c];
                if (RELU) o[c] = fmaxf(o[c], 0.f);
            }
            float* op = out + row*DD + tx*8;
            *(float4*)op       = make_float4(o[0], o[1], o[2], o[3]);
            *(float4*)(op + 4) = make_float4(o[4], o[5], o[6], o[7]);
        }
    }
}

// ---------------- launch ----------------
extern "C" void kernel_launch(void* const* d_in, const int* in_sizes, int n_in,
                              void* d_out, int out_size) {
    const float* x  = (const float*)d_in[0];
    const void*  ei = d_in[1];
    const float* Wl = (const float*)d_in[2];
    const float* bl = (const float*)d_in[3];
    const float* Wr = (const float*)d_in[4];
    const float* W  = (const float*)d_in[5];
    const float* b  = (const float*)d_in[6];
    float* out = (float*)d_out;

    void *pa, *p1, *p2, *pl, *pr, *pw;
    cudaGetSymbolAddress(&pa, g_agg);
    cudaGetSymbolAddress(&p1, g_x1);
    cudaGetSymbolAddress(&p2, g_x2);
    cudaGetSymbolAddress(&pl, g_WlT);
    cudaGetSymbolAddress(&pr, g_WrT);
    cudaGetSymbolAddress(&pw, g_WT);
    float* agg = (float*)pa;
    float* x1  = (float*)p1;
    float* x2  = (float*)p2;
    float* WlT = (float*)pl;
    float* WrT = (float*)pr;
    float* WT  = (float*)pw;

    const int smem2 = 3*NMAT*(int)sizeof(float);   // 196608
    const int smem1 = 2*NMAT*(int)sizeof(float);   // 131072
    cudaFuncSetAttribute(k_gemm<true,true>,   cudaFuncAttributeMaxDynamicSharedMemorySize, smem2);
    cudaFuncSetAttribute(k_gemm<false,false>, cudaFuncAttributeMaxDynamicSharedMemorySize, smem1);

    // CSR build
    k_init   <<<98, 512>>>(ei);
    k_count  <<<(EE+511)/512, 512>>>(ei);
    k_scan1  <<<NBLK, SCAN_B>>>();
    k_scan2  <<<1, 64>>>();
    k_scan3  <<<NBLK, SCAN_B>>>();
    k_scatter<<<(EE+511)/512, 512>>>(ei);

    // weight transposes (all 5 matrices, one launch)
    k_transpose<<<dim3(16,5), dim3(32,8)>>>(Wl, Wr, W);

    const int gemm_blocks = (NN + 127) / 128;

    // layer 0
    k_aggregate<<<(NN+7)/8, 256>>>(x, agg);
    k_gemm<true,true><<<gemm_blocks, 256, smem2>>>(agg, x, WlT, WrT, bl, x1, NN);
    // layer 1
    k_aggregate<<<(NN+7)/8, 256>>>(x1, agg);
    k_gemm<true,true><<<gemm_blocks, 256, smem2>>>(agg, x1, WlT+NMAT, WrT+NMAT, bl+DD, x2, NN);
    // final linear
    k_gemm<false,false><<<gemm_blocks, 256, smem1>>>(x2, nullptr, WT, nullptr, b, out, NN);
}

// round 5
// speedup vs baseline: 1.7813x; 1.4715x over previous
#include <cuda_runtime.h>
#include <cuda_bf16.h>
#include <cstdint>

#define NN 50000
#define EE 800000
#define DD 128
#define NMAT (DD*DD)
#define SCAN_B 1024
#define NBLK ((NN + SCAN_B - 1) / SCAN_B)   // 49

#define AST 136                 // padded row stride (bf16 elems) -> conflict-free ldmatrix
#define PL  (128*AST)           // plane elems (17408)
#define PLB (PL*2)              // plane bytes (34816)

// ---------------- scratch (static device globals; no runtime alloc) ----------------
__device__ float g_agg[NN*DD];
__device__ float g_x1[NN*DD];
__device__ float g_x2[NN*DD];
__device__ int   g_cnt[NN];
__device__ int   g_off[NN+1];
__device__ int   g_cursor[NN];
__device__ int   g_csr[EE];
__device__ int   g_bsum[64];
__device__ int   g_bbase[64];
__device__ __nv_bfloat16 g_Wbf[5*2*PL];   // 5 matrices x {hi,lo} planes, padded layout
__device__ int   g_is64;

// ---------------- helpers ----------------
__device__ __forceinline__ uint32_t smem_u32(const void* p) {
    uint32_t a;
    asm("{ .reg .u64 t; cvta.to.shared.u64 t, %1; cvt.u32.u64 %0, t; }" : "=r"(a) : "l"(p));
    return a;
}
__device__ __forceinline__ unsigned pkbf(__nv_bfloat16 a, __nv_bfloat16 b) {
    return (unsigned)__bfloat16_as_ushort(a) | ((unsigned)__bfloat16_as_ushort(b) << 16);
}

#define LDSM4(r, addr) \
    asm volatile("ldmatrix.sync.aligned.m8n8.x4.shared.b16 {%0,%1,%2,%3}, [%4];" \
        : "=r"((r)[0]), "=r"((r)[1]), "=r"((r)[2]), "=r"((r)[3]) : "r"(addr))

#define MMA(d, a, b0, b1) \
    asm volatile("mma.sync.aligned.m16n8k16.row.col.f32.bf16.bf16.f32 " \
        "{%0,%1,%2,%3}, {%4,%5,%6,%7}, {%8,%9}, {%0,%1,%2,%3};" \
        : "+f"((d)[0]), "+f"((d)[1]), "+f"((d)[2]), "+f"((d)[3]) \
        : "r"((a)[0]), "r"((a)[1]), "r"((a)[2]), "r"((a)[3]), "r"(b0), "r"(b1))

// ---------------- init: dtype detection (parallel) + zero counters ----------------
__global__ void k_init(const void* __restrict__ ei) {
    __shared__ int s_ok[2];
    int tid = threadIdx.x;
    if (blockIdx.x == 0) {
        if (tid < 64) {
            long long v = ((const long long*)ei)[tid];
            unsigned ok = (v >= 0 && v < NN) ? 1u : 0u;
            unsigned m = __ballot_sync(0xffffffffu, ok);
            if ((tid & 31) == 0) s_ok[tid >> 5] = (m == 0xffffffffu);
        }
        __syncthreads();
        if (tid == 0) g_is64 = s_ok[0] & s_ok[1];
    }
    for (int i = blockIdx.x*blockDim.x + tid; i < NN; i += gridDim.x*blockDim.x)
        g_cnt[i] = 0;
}

__device__ __forceinline__ int load_idx(const void* ei, int pos, int is64) {
    if (is64) return (int)((const long long*)ei)[pos];
    return ((const int*)ei)[pos];
}

__global__ void k_count(const void* __restrict__ ei) {
    int i = blockIdx.x*blockDim.x + threadIdx.x;
    if (i < EE) {
        int dst = load_idx(ei, EE + i, g_is64);
        if ((unsigned)dst < NN) atomicAdd(&g_cnt[dst], 1);
    }
}

// ---------------- multi-block exclusive scan ----------------
__global__ void k_scan1() {
    __shared__ int wsum[32];
    int tid  = threadIdx.x;
    int lane = tid & 31, wid = tid >> 5;
    int i = blockIdx.x*SCAN_B + tid;
    int v = (i < NN) ? g_cnt[i] : 0;
    int s = v;
    #pragma unroll
    for (int d = 1; d < 32; d <<= 1) {
        int t = __shfl_up_sync(0xffffffffu, s, d);
        if (lane >= d) s += t;
    }
    if (lane == 31) wsum[wid] = s;
    __syncthreads();
    if (wid == 0) {
        int ws = wsum[lane];
        #pragma unroll
        for (int d = 1; d < 32; d <<= 1) {
            int t = __shfl_up_sync(0xffffffffu, ws, d);
            if (lane >= d) ws += t;
        }
        wsum[lane] = ws;
    }
    __syncthreads();
    int incl = s + ((wid > 0) ? wsum[wid-1] : 0);
    if (i < NN) g_off[i+1] = incl;
    if (tid == SCAN_B-1) g_bsum[blockIdx.x] = incl;
}

__global__ void k_scan2() {
    __shared__ int sh[64];
    int tid = threadIdx.x;
    int v = (tid < NBLK) ? g_bsum[tid] : 0;
    sh[tid] = v;
    __syncthreads();
    #pragma unroll
    for (int s = 1; s < 64; s <<= 1) {
        int t = (tid >= s) ? sh[tid - s] : 0;
        __syncthreads();
        sh[tid] += t;
        __syncthreads();
    }
    if (tid < NBLK) g_bbase[tid] = sh[tid] - v;
}

__global__ void k_scan3() {
    int i = blockIdx.x*SCAN_B + threadIdx.x;
    if (i < NN) {
        int incl = g_off[i+1] + g_bbase[blockIdx.x];
        g_off[i+1]  = incl;
        g_cursor[i] = incl - g_cnt[i];
    }
    if (i == 0) g_off[0] = 0;
}

__global__ void k_scatter(const void* __restrict__ ei) {
    int i = blockIdx.x*blockDim.x + threadIdx.x;
    if (i < EE) {
        int is64 = g_is64;
        int src = load_idx(ei, i, is64);
        int dst = load_idx(ei, EE + i, is64);
        if ((unsigned)dst < NN && (unsigned)src < NN) {
            int pos = atomicAdd(&g_cursor[dst], 1);
            if ((unsigned)pos < EE) g_csr[pos] = src;
        }
    }
}

// ---------------- weight split fp32 -> bf16 hi/lo, padded smem image ----------------
__global__ void k_wconv(const float* __restrict__ Wl, const float* __restrict__ Wr,
                        const float* __restrict__ W) {
    int m = blockIdx.x;   // 0,1: Wl  2,3: Wr  4: W
    const float* src = (m < 2) ? Wl + m*NMAT : ((m < 4) ? Wr + (m-2)*NMAT : W);
    __nv_bfloat16* hi = g_Wbf + (size_t)m*2*PL;
    __nv_bfloat16* lo = hi + PL;
    for (int idx = threadIdx.x; idx < NMAT; idx += blockDim.x) {
        int row = idx >> 7, k = idx & 127;    // row = out-feature n, k = in-feature
        float x = src[idx];
        __nv_bfloat16 h = __float2bfloat16(x);
        __nv_bfloat16 l = __float2bfloat16(x - __bfloat162float(h));
        hi[row*AST + k] = h;
        lo[row*AST + k] = l;
    }
}

// ---------------- max-aggregation: one warp per node, float4 per lane ----------------
__global__ void k_aggregate(const float* __restrict__ x, float* __restrict__ agg) {
    int w    = blockIdx.x * 8 + (threadIdx.x >> 5);
    int lane = threadIdx.x & 31;
    if (w >= NN) return;
    int beg = g_off[w], end = g_off[w+1];
    const float NEG = __int_as_float(0xff800000);
    float4 m = make_float4(NEG, NEG, NEG, NEG);
    const float4* xv = (const float4*)x;
    int e = beg;
    for (; e + 4 <= end; e += 4) {
        int s0 = g_csr[e], s1 = g_csr[e+1], s2 = g_csr[e+2], s3 = g_csr[e+3];
        float4 v0 = xv[s0*32 + lane];
        float4 v1 = xv[s1*32 + lane];
        float4 v2 = xv[s2*32 + lane];
        float4 v3 = xv[s3*32 + lane];
        m.x = fmaxf(m.x, fmaxf(fmaxf(v0.x, v1.x), fmaxf(v2.x, v3.x)));
        m.y = fmaxf(m.y, fmaxf(fmaxf(v0.y, v1.y), fmaxf(v2.y, v3.y)));
        m.z = fmaxf(m.z, fmaxf(fmaxf(v0.z, v1.z), fmaxf(v2.z, v3.z)));
        m.w = fmaxf(m.w, fmaxf(fmaxf(v0.w, v1.w), fmaxf(v2.w, v3.w)));
    }
    for (; e < end; e++) {
        int s = g_csr[e];
        float4 v = xv[s*32 + lane];
        m.x = fmaxf(m.x, v.x);
        m.y = fmaxf(m.y, v.y);
        m.z = fmaxf(m.z, v.z);
        m.w = fmaxf(m.w, v.w);
    }
    if (beg == end) m = make_float4(0.f, 0.f, 0.f, 0.f);
    ((float4*)agg)[w*32 + lane] = m;
}

// ---------------- tensor-core GEMM via mma.sync bf16-split ----------------
// out = relu?( A1 @ W1^T [+ A2 @ W2^T] + bias ),  A*B ~ Ahi*Bhi + Ahi*Blo + Alo*Bhi

__device__ __forceinline__ void conv_tile(const float* __restrict__ src, char* hi, char* lo,
                                          int row0, int nrows) {
    int tid = threadIdx.x;
    #pragma unroll
    for (int it = 0; it < 16; it++) {
        int fidx = it*256 + tid;            // 4096 float4s = 128 rows x 32
        int row = fidx >> 5;
        int kq  = (fidx & 31) * 4;
        float4 v = make_float4(0.f, 0.f, 0.f, 0.f);
        if (row0 + row < nrows) v = ((const float4*)src)[(row0 + row)*32 + (fidx & 31)];
        __nv_bfloat16 h0 = __float2bfloat16(v.x);
        __nv_bfloat16 h1 = __float2bfloat16(v.y);
        __nv_bfloat16 h2 = __float2bfloat16(v.z);
        __nv_bfloat16 h3 = __float2bfloat16(v.w);
        __nv_bfloat16 l0 = __float2bfloat16(v.x - __bfloat162float(h0));
        __nv_bfloat16 l1 = __float2bfloat16(v.y - __bfloat162float(h1));
        __nv_bfloat16 l2 = __float2bfloat16(v.z - __bfloat162float(h2));
        __nv_bfloat16 l3 = __float2bfloat16(v.w - __bfloat162float(h3));
        uint32_t off = (uint32_t)(row*AST + kq) * 2u;   // 8B aligned
        *(uint2*)(hi + off) = make_uint2(pkbf(h0, h1), pkbf(h2, h3));
        *(uint2*)(lo + off) = make_uint2(pkbf(l0, l1), pkbf(l2, l3));
    }
}

__device__ __forceinline__ void pass_pair(float acc[4][4][4],
                                          uint32_t aHi, uint32_t aLo,
                                          uint32_t wHi, uint32_t wLo,
                                          const uint32_t* aoff, const uint32_t* woff) {
    #pragma unroll 1
    for (int ks = 0; ks < 8; ks++) {
        uint32_t kb = (uint32_t)ks * 32u;   // 16 bf16 per k-step
        uint32_t ah[4][4], al[4][4], wh[2][4], wl[2][4];
        #pragma unroll
        for (int mt = 0; mt < 4; mt++) {
            LDSM4(ah[mt], aHi + aoff[mt] + kb);
            LDSM4(al[mt], aLo + aoff[mt] + kb);
        }
        #pragma unroll
        for (int c = 0; c < 2; c++) {
            LDSM4(wh[c], wHi + woff[c] + kb);
            LDSM4(wl[c], wLo + woff[c] + kb);
        }
        #pragma unroll
        for (int mt = 0; mt < 4; mt++) {
            #pragma unroll
            for (int c = 0; c < 2; c++) {
                MMA(acc[mt][2*c],   ah[mt], wh[c][0], wh[c][1]);
                MMA(acc[mt][2*c+1], ah[mt], wh[c][2], wh[c][3]);
                MMA(acc[mt][2*c],   ah[mt], wl[c][0], wl[c][1]);
                MMA(acc[mt][2*c+1], ah[mt], wl[c][2], wl[c][3]);
                MMA(acc[mt][2*c],   al[mt], wh[c][0], wh[c][1]);
                MMA(acc[mt][2*c+1], al[mt], wh[c][2], wh[c][3]);
            }
        }
    }
}

template<bool HAS2, bool RELU>
__global__ __launch_bounds__(256)
void k_gemm_mma(const float* __restrict__ A1, const float* __restrict__ A2,
                const __nv_bfloat16* __restrict__ Wimg1, const __nv_bfloat16* __restrict__ Wimg2,
                const float* __restrict__ bias, float* __restrict__ out, int nrows)
{
    extern __shared__ char sm[];
    char* Ahi = sm;
    char* Alo = sm + PLB;
    char* W1  = sm + 2*PLB;     // hi plane then lo plane
    char* W2  = sm + 4*PLB;

    int tid = threadIdx.x;
    // copy weight images (already split + padded) into smem, once per CTA
    {
        const float4* s1 = (const float4*)Wimg1;
        float4* d1 = (float4*)W1;
        for (int i = tid; i < 2*PLB/16; i += 256) d1[i] = s1[i];
        if (HAS2) {
            const float4* s2 = (const float4*)Wimg2;
            float4* d2 = (float4*)W2;
            for (int i = tid; i < 2*PLB/16; i += 256) d2[i] = s2[i];
        }
    }

    int wid = tid >> 5, lane = tid & 31;
    int wm = wid & 1, wn = wid >> 1;     // warp tile: 64 rows x 32 cols

    // ldmatrix per-lane fragment offsets (bytes within a plane)
    uint32_t aoff[4], woff[2];
    {
        int kL = (lane >> 4) * 8;
        #pragma unroll
        for (int mt = 0; mt < 4; mt++) {
            int m = wm*64 + mt*16 + ((lane >> 3) & 1)*8 + (lane & 7);
            aoff[mt] = (uint32_t)(m*AST + kL) * 2u;
        }
        int kW = ((lane >> 3) & 1) * 8;
        #pragma unroll
        for (int c = 0; c < 2; c++) {
            int n = wn*32 + c*16 + (lane >> 4)*8 + (lane & 7);
            woff[c] = (uint32_t)(n*AST + kW) * 2u;
        }
    }
    uint32_t sAhi = smem_u32(Ahi), sAlo = smem_u32(Alo);
    uint32_t sW1h = smem_u32(W1),  sW1l = sW1h + PLB;
    uint32_t sW2h = smem_u32(W2),  sW2l = sW2h + PLB;

    int g = lane >> 2, t4 = lane & 3;
    const int ntiles = (nrows + 127) / 128;

    for (int tile = blockIdx.x; tile < ntiles; tile += gridDim.x) {
        int row0 = tile * 128;

        __syncthreads();                       // prior tile's reads done
        conv_tile(A1, Ahi, Alo, row0, nrows);
        __syncthreads();

        float acc[4][4][4];
        #pragma unroll
        for (int a = 0; a < 4; a++)
            #pragma unroll
            for (int b = 0; b < 4; b++)
                #pragma unroll
                for (int c = 0; c < 4; c++) acc[a][b][c] = 0.f;

        pass_pair(acc, sAhi, sAlo, sW1h, sW1l, aoff, woff);

        if (HAS2) {
            __syncthreads();
            conv_tile(A2, Ahi, Alo, row0, nrows);
            __syncthreads();
            pass_pair(acc, sAhi, sAlo, sW2h, sW2l, aoff, woff);
        }

        // epilogue: bias + relu + store
        #pragma unroll
        for (int mt = 0; mt < 4; mt++) {
            int row = row0 + wm*64 + mt*16 + g;
            #pragma unroll
            for (int nt = 0; nt < 4; nt++) {
                int col = wn*32 + nt*8 + t4*2;
                float2 bb = *(const float2*)(bias + col);
                float r0 = acc[mt][nt][0] + bb.x;
                float r1 = acc[mt][nt][1] + bb.y;
                float r2 = acc[mt][nt][2] + bb.x;
                float r3 = acc[mt][nt][3] + bb.y;
                if (RELU) {
                    r0 = fmaxf(r0, 0.f); r1 = fmaxf(r1, 0.f);
                    r2 = fmaxf(r2, 0.f); r3 = fmaxf(r3, 0.f);
                }
                if (row < nrows)
                    *(float2*)(out + (size_t)row*DD + col) = make_float2(r0, r1);
                if (row + 8 < nrows)
                    *(float2*)(out + (size_t)(row + 8)*DD + col) = make_float2(r2, r3);
            }
        }
    }
}

// ---------------- launch ----------------
extern "C" void kernel_launch(void* const* d_in, const int* in_sizes, int n_in,
                              void* d_out, int out_size) {
    const float* x  = (const float*)d_in[0];
    const void*  ei = d_in[1];
    const float* Wl = (const float*)d_in[2];
    const float* bl = (const float*)d_in[3];
    const float* Wr = (const float*)d_in[4];
    const float* W  = (const float*)d_in[5];
    const float* b  = (const float*)d_in[6];
    float* out = (float*)d_out;

    void *pa, *p1, *p2, *pw;
    cudaGetSymbolAddress(&pa, g_agg);
    cudaGetSymbolAddress(&p1, g_x1);
    cudaGetSymbolAddress(&p2, g_x2);
    cudaGetSymbolAddress(&pw, g_Wbf);
    float* agg = (float*)pa;
    float* x1  = (float*)p1;
    float* x2  = (float*)p2;
    __nv_bfloat16* Wbf = (__nv_bfloat16*)pw;
    // matrix images: 0=Wl0 1=Wl1 2=Wr0 3=Wr1 4=W, each 2*PL bf16 (hi+lo planes)
    __nv_bfloat16* M0 = Wbf;
    __nv_bfloat16* M1 = Wbf + 1*2*PL;
    __nv_bfloat16* M2 = Wbf + 2*2*PL;
    __nv_bfloat16* M3 = Wbf + 3*2*PL;
    __nv_bfloat16* M4 = Wbf + 4*2*PL;

    const int smem2 = 6*PLB;   // 208896
    const int smem1 = 4*PLB;   // 139264
    cudaFuncSetAttribute(k_gemm_mma<true,true>,   cudaFuncAttributeMaxDynamicSharedMemorySize, smem2);
    cudaFuncSetAttribute(k_gemm_mma<false,false>, cudaFuncAttributeMaxDynamicSharedMemorySize, smem1);

    // CSR build
    k_init   <<<98, 512>>>(ei);
    k_count  <<<(EE+511)/512, 512>>>(ei);
    k_scan1  <<<NBLK, SCAN_B>>>();
    k_scan2  <<<1, 64>>>();
    k_scan3  <<<NBLK, SCAN_B>>>();
    k_scatter<<<(EE+511)/512, 512>>>(ei);

    // weight split + pad (5 matrices)
    k_wconv<<<5, 256>>>(Wl, Wr, W);

    // layer 0
    k_aggregate<<<(NN+7)/8, 256>>>(x, agg);
    k_gemm_mma<true,true><<<148, 256, smem2>>>(agg, x, M0, M2, bl, x1, NN);
    // layer 1
    k_aggregate<<<(NN+7)/8, 256>>>(x1, agg);
    k_gemm_mma<true,true><<<148, 256, smem2>>>(agg, x1, M1, M3, bl+DD, x2, NN);
    // final linear
    k_gemm_mma<false,false><<<148, 256, smem1>>>(x2, nullptr, M4, nullptr, b, out, NN);
}